// round 1
// baseline (speedup 1.0000x reference)
#include <cuda_runtime.h>

#define B_    64
#define HH    56
#define WW    56
#define C_    96
#define NTOK  49
#define HEADS_ 3
#define HD    32
#define M_TOK (B_*HH*WW)   // 200704
#define QKV_N 288

// Scratch (allocation-free rule: __device__ globals)
__device__ float g_qkv[(size_t)M_TOK * QKV_N];   // 231 MB
__device__ float g_att[(size_t)M_TOK * C_];      //  77 MB

// out[M,N] = A[M,96] @ Bw[96,N] + bias[N]; tile 64(M) x 96(N), full K=96.
__global__ __launch_bounds__(256) void gemm_bias_kernel(
    const float* __restrict__ A, const float* __restrict__ Bw,
    const float* __restrict__ bias, float* __restrict__ out, int N)
{
    __shared__ float sAT[96][65];   // A tile transposed [k][m], padded
    __shared__ float sB[96][96];    // B tile [k][n]
    const int m0 = blockIdx.x * 64;
    const int n0 = blockIdx.y * 96;
    const int tid = threadIdx.x;

    // Load A tile (64 x 96), store transposed (coalesced gmem reads)
    for (int i = tid; i < 64 * 96; i += 256) {
        int row = i / 96, k = i - row * 96;
        sAT[k][row] = A[(size_t)(m0 + row) * 96 + k];
    }
    // Load B tile (96 x 96) vectorized
    for (int i = tid; i < 96 * 24; i += 256) {
        int k = i / 24, c4 = i - k * 24;
        ((float4*)sB[k])[c4] = ((const float4*)(Bw + (size_t)k * N + n0))[c4];
    }
    __syncthreads();

    const int tx = tid & 15, ty = tid >> 4;   // 16 x 16 threads -> 4x6 regs each
    float acc[4][6];
    #pragma unroll
    for (int r = 0; r < 4; r++)
        #pragma unroll
        for (int c = 0; c < 6; c++) acc[r][c] = 0.f;

    #pragma unroll 8
    for (int k = 0; k < 96; k++) {
        float a[4], b[6];
        #pragma unroll
        for (int r = 0; r < 4; r++) a[r] = sAT[k][ty * 4 + r];
        #pragma unroll
        for (int c = 0; c < 6; c++) b[c] = sB[k][tx * 6 + c];
        #pragma unroll
        for (int r = 0; r < 4; r++)
            #pragma unroll
            for (int c = 0; c < 6; c++) acc[r][c] += a[r] * b[c];
    }

    #pragma unroll
    for (int r = 0; r < 4; r++) {
        int row = m0 + ty * 4 + r;
        #pragma unroll
        for (int c = 0; c < 6; c++) {
            int col = n0 + tx * 6 + c;
            out[(size_t)row * N + col] = acc[r][c] + bias[col];
        }
    }
}

// One block per (window, head). Gathers strided Swin tokens, does softmax
// attention with on-the-fly relative-position bias, scatters to spatial layout.
__global__ __launch_bounds__(128) void attn_kernel(const float* __restrict__ rel_pos)
{
    const int win  = blockIdx.x;           // 0..4095 = ((b*8)+hi)*8+wi
    const int head = blockIdx.y;           // 0..2
    const int wi = win & 7, hi = (win >> 3) & 7, b = win >> 6;

    __shared__ float sq[NTOK][33], sk[NTOK][33], sv[NTOK][33];
    __shared__ float ssim[NTOK][49];
    __shared__ int   sg[NTOK];
    const int tid = threadIdx.x;

    if (tid < NTOK) {
        int p = tid / 7, q = tid - (tid / 7) * 7;
        // token (p,q) of window (hi,wi) lives at spatial (p*8+hi, q*8+wi)
        sg[tid] = (b * 56 + p * 8 + hi) * 56 + q * 8 + wi;
    }
    __syncthreads();

    const float scale = 0.17677669529663687f;  // 32^-0.5
    for (int i = tid; i < NTOK * HD; i += 128) {
        int t = i >> 5, d = i & 31;
        size_t base = (size_t)sg[t] * QKV_N + head * HD + d;
        sq[t][d] = g_qkv[base]       * scale;
        sk[t][d] = g_qkv[base + 96];
        sv[t][d] = g_qkv[base + 192];
    }
    __syncthreads();

    // sim = q k^T + bias
    for (int e = tid; e < NTOK * NTOK; e += 128) {
        int i = e / 49, j = e - i * 49;
        float s = 0.f;
        #pragma unroll
        for (int d = 0; d < HD; d++) s += sq[i][d] * sk[j][d];
        int pi = i / 7, qi = i - pi * 7;
        int pj = j / 7, qj = j - pj * 7;
        int ridx = (pi - pj + 6) * 13 + (qi - qj + 6);
        ssim[i][j] = s + rel_pos[head * 169 + ridx];
    }
    __syncthreads();

    // softmax, one row per thread
    if (tid < NTOK) {
        float mx = -1e30f;
        for (int j = 0; j < 49; j++) mx = fmaxf(mx, ssim[tid][j]);
        float sum = 0.f;
        for (int j = 0; j < 49; j++) {
            float e = __expf(ssim[tid][j] - mx);
            ssim[tid][j] = e;
            sum += e;
        }
        float inv = 1.f / sum;
        for (int j = 0; j < 49; j++) ssim[tid][j] *= inv;
    }
    __syncthreads();

    // out = att @ v, scatter to spatial layout
    for (int e = tid; e < NTOK * HD; e += 128) {
        int i = e >> 5, d = e & 31;
        float s = 0.f;
        #pragma unroll
        for (int j = 0; j < 49; j++) s += ssim[i][j] * sv[j][d];
        g_att[(size_t)sg[i] * C_ + head * HD + d] = s;
    }
}

extern "C" void kernel_launch(void* const* d_in, const int* in_sizes, int n_in,
                              void* d_out, int out_size)
{
    (void)in_sizes; (void)n_in; (void)out_size;
    const float* x      = (const float*)d_in[0];
    const float* w_qkv  = (const float*)d_in[1];
    const float* b_qkv  = (const float*)d_in[2];
    const float* rel    = (const float*)d_in[3];
    const float* w_out  = (const float*)d_in[4];
    const float* b_out  = (const float*)d_in[5];
    float* out = (float*)d_out;

    float *qkv_p = nullptr, *att_p = nullptr;
    cudaGetSymbolAddress((void**)&qkv_p, g_qkv);
    cudaGetSymbolAddress((void**)&att_p, g_att);

    // 1) qkv = x @ w_qkv + b_qkv   (M=200704, N=288, K=96)
    dim3 gA(M_TOK / 64, QKV_N / 96);
    gemm_bias_kernel<<<gA, 256>>>(x, w_qkv, b_qkv, qkv_p, QKV_N);

    // 2) windowed attention, scatter to spatial layout
    dim3 gB(4096, HEADS_);
    attn_kernel<<<gB, 128>>>(rel);

    // 3) out = att @ w_out + b_out  (N=96)
    dim3 gC(M_TOK / 64, 1);
    gemm_bias_kernel<<<gC, 256>>>(att_p, w_out, b_out, out, 96);
}

// round 2
// speedup vs baseline: 1.2057x; 1.2057x over previous
#include <cuda_runtime.h>

#define M_TOK 200704
#define QKV_N 288

// Scratch (allocation-free rule: __device__ globals)
__device__ float g_qkv[(size_t)M_TOK * QKV_N];   // 231 MB
__device__ float g_att[(size_t)M_TOK * 96];      //  77 MB

typedef unsigned long long u64;

__device__ __forceinline__ u64 pack2(float lo, float hi) {
    u64 r; asm("mov.b64 %0,{%1,%2};" : "=l"(r) : "f"(lo), "f"(hi)); return r;
}
__device__ __forceinline__ void ffma2(u64& d, u64 a, u64 b) {
    asm("fma.rn.f32x2 %0,%1,%2,%0;" : "+l"(d) : "l"(a), "l"(b));
}

// ---------------------------------------------------------------------------
// GEMM: out[M,N] = A[M,96] @ Bw[96,N] + bias.  Tile 128(M) x 96(N), K=96 full.
// 192 threads, each 8 rows x 8 cols via FFMA2 (pairs along M).
// Columns per thread strided by 12 -> conflict-free B loads.
// dynamic smem: sAT[96][130] + sB[96][96] = 86784 B
// ---------------------------------------------------------------------------
#define GEMM_SMEM ((96*130 + 96*96) * 4)

__global__ __launch_bounds__(192) void gemm_f32x2(
    const float* __restrict__ A, const float* __restrict__ Bw,
    const float* __restrict__ bias, float* __restrict__ out, int N)
{
    extern __shared__ float smem[];
    float* sAT = smem;               // [k][m], row stride 130 (even -> LDS.64 ok)
    float* sB  = smem + 96 * 130;    // [k][n], row stride 96
    const int m0 = blockIdx.x * 128;
    const int n0 = blockIdx.y * 96;
    const int tid = threadIdx.x;

    // A tile 128x96, transposed into smem (coalesced float4 gmem reads)
    for (int i = tid; i < 128 * 24; i += 192) {
        int row = i / 24, k4 = (i % 24) * 4;
        float4 v = *(const float4*)(A + (size_t)(m0 + row) * 96 + k4);
        sAT[(k4 + 0) * 130 + row] = v.x;
        sAT[(k4 + 1) * 130 + row] = v.y;
        sAT[(k4 + 2) * 130 + row] = v.z;
        sAT[(k4 + 3) * 130 + row] = v.w;
    }
    // B tile 96x96
    for (int i = tid; i < 96 * 24; i += 192) {
        int k = i / 24, c4 = (i % 24) * 4;
        *(float4*)(sB + k * 96 + c4) = *(const float4*)(Bw + (size_t)k * N + n0 + c4);
    }
    __syncthreads();

    const int tx = tid % 12;         // col group: cols tx + 12*c
    const int ty = tid / 12;         // row group: rows ty*8 .. ty*8+7
    u64 acc[4][8];
    #pragma unroll
    for (int r = 0; r < 4; r++)
        #pragma unroll
        for (int c = 0; c < 8; c++) acc[r][c] = 0ull;

    const float* aBase = sAT + ty * 8;
    const float* bBase = sB + tx;

    #pragma unroll 4
    for (int k = 0; k < 96; k++) {
        u64 a[4];
        #pragma unroll
        for (int r = 0; r < 4; r++)
            a[r] = *(const u64*)(aBase + k * 130 + 2 * r);   // LDS.64: rows 2r,2r+1
        u64 b[8];
        #pragma unroll
        for (int c = 0; c < 8; c++) {
            float bv = bBase[k * 96 + 12 * c];
            b[c] = pack2(bv, bv);
        }
        #pragma unroll
        for (int r = 0; r < 4; r++)
            #pragma unroll
            for (int c = 0; c < 8; c++) ffma2(acc[r][c], a[r], b[c]);
    }

    #pragma unroll
    for (int c = 0; c < 8; c++) {
        int col = n0 + tx + 12 * c;
        float bb = bias[col];
        #pragma unroll
        for (int r = 0; r < 4; r++) {
            float lo, hi;
            asm("mov.b64 {%0,%1},%2;" : "=f"(lo), "=f"(hi) : "l"(acc[r][c]));
            size_t base = (size_t)(m0 + ty * 8 + 2 * r) * N + col;
            out[base]     = lo + bb;
            out[base + N] = hi + bb;
        }
    }
}

// ---------------------------------------------------------------------------
// Attention: one block per window (all 3 heads), 192 threads.
// sim: 7x7 register tiles (147 threads).  AV: 7i x 4d tiles (168 threads).
// dynamic smem: 3 * (3*49*33) + 3*49*50 + 507 floats = 89640 B
// ---------------------------------------------------------------------------
#define ATTN_SMEM ((3*(3*49*33) + 3*49*50 + 507) * 4)

__global__ __launch_bounds__(192) void attn2(const float* __restrict__ rel_pos)
{
    extern __shared__ float sm[];
    float* sq   = sm;                         // [h][49][33]
    float* sk   = sq + 3 * 49 * 33;
    float* sv   = sk + 3 * 49 * 33;
    float* ssim = sv + 3 * 49 * 33;           // [h][49][50]
    float* srel = ssim + 3 * 49 * 50;         // [507]
    __shared__ int sg[49];

    const int tid = threadIdx.x;
    const int win = blockIdx.x;               // ((b*8)+hi)*8+wi
    const int wi = win & 7, hi = (win >> 3) & 7, b = win >> 6;

    if (tid < 49) {
        int p = tid / 7, q = tid - (tid / 7) * 7;
        sg[tid] = (b * 56 + p * 8 + hi) * 56 + q * 8 + wi;   // spatial token idx
    }
    for (int i = tid; i < 507; i += 192) srel[i] = rel_pos[i];
    __syncthreads();

    const float scale = 0.17677669529663687f;  // 32^-0.5
    // Gather q,k,v for all heads: 49 tokens * 3 heads * 3 mats * 8 float4
    for (int i = tid; i < 49 * 72; i += 192) {
        int t = i / 72, r = i % 72, h = r / 24, u = r % 24;
        int which = u / 8, d4 = (u % 8) * 4;
        float4 v = *(const float4*)(g_qkv + (size_t)sg[t] * 288 + which * 96 + h * 32 + d4);
        float* dst = (which == 0 ? sq : which == 1 ? sk : sv) + (h * 49 + t) * 33 + d4;
        if (which == 0) {
            dst[0] = v.x * scale; dst[1] = v.y * scale;
            dst[2] = v.z * scale; dst[3] = v.w * scale;
        } else {
            dst[0] = v.x; dst[1] = v.y; dst[2] = v.z; dst[3] = v.w;
        }
    }
    __syncthreads();

    // sim = q k^T + bias : thread = (head, 7x7 tile)
    if (tid < 147) {
        int h = tid / 49, s = tid % 49, ti = s / 7, tj = s % 7;
        const float* qb = sq + (h * 49 + ti * 7) * 33;
        const float* kb = sk + (h * 49 + tj * 7) * 33;
        float acc[7][7];
        #pragma unroll
        for (int r = 0; r < 7; r++)
            #pragma unroll
            for (int c = 0; c < 7; c++) acc[r][c] = 0.f;
        #pragma unroll 4
        for (int d = 0; d < 32; d++) {
            float qr[7], kc[7];
            #pragma unroll
            for (int r = 0; r < 7; r++) qr[r] = qb[r * 33 + d];
            #pragma unroll
            for (int c = 0; c < 7; c++) kc[c] = kb[c * 33 + d];
            #pragma unroll
            for (int r = 0; r < 7; r++)
                #pragma unroll
                for (int c = 0; c < 7; c++) acc[r][c] += qr[r] * kc[c];
        }
        // token i = ti*7+r -> (p,q) = (ti, r); j = tj*7+c -> (tj, c)
        const float* relh = srel + h * 169;
        float* simb = ssim + (h * 49 + ti * 7) * 50 + tj * 7;
        #pragma unroll
        for (int r = 0; r < 7; r++)
            #pragma unroll
            for (int c = 0; c < 7; c++)
                simb[r * 50 + c] = acc[r][c] + relh[(ti - tj + 6) * 13 + (r - c + 6)];
    }
    __syncthreads();

    // softmax: one row per thread
    if (tid < 147) {
        int h = tid / 49, i = tid % 49;
        float* row = ssim + (h * 49 + i) * 50;
        float mx = -1e30f;
        #pragma unroll
        for (int j = 0; j < 49; j++) mx = fmaxf(mx, row[j]);
        float sum = 0.f;
        #pragma unroll
        for (int j = 0; j < 49; j++) { float e = __expf(row[j] - mx); row[j] = e; sum += e; }
        float inv = 1.f / sum;
        #pragma unroll
        for (int j = 0; j < 49; j++) row[j] *= inv;
    }
    __syncthreads();

    // out = att @ v : thread = (head, 7-row tile, 4-col d chunk), scatter float4
    if (tid < 168) {
        int h = tid / 56, s = tid % 56, ti = s / 8, td = s % 8;
        float acc[7][4];
        #pragma unroll
        for (int r = 0; r < 7; r++)
            #pragma unroll
            for (int c = 0; c < 4; c++) acc[r][c] = 0.f;
        const float* attb = ssim + (h * 49 + ti * 7) * 50;
        const float* vb   = sv + h * 49 * 33 + td * 4;
        #pragma unroll 7
        for (int j = 0; j < 49; j++) {
            float vv[4];
            #pragma unroll
            for (int c = 0; c < 4; c++) vv[c] = vb[j * 33 + c];
            #pragma unroll
            for (int r = 0; r < 7; r++) {
                float a = attb[r * 50 + j];
                #pragma unroll
                for (int c = 0; c < 4; c++) acc[r][c] += a * vv[c];
            }
        }
        #pragma unroll
        for (int r = 0; r < 7; r++) {
            int i = ti * 7 + r;
            float4 o = make_float4(acc[r][0], acc[r][1], acc[r][2], acc[r][3]);
            *(float4*)(g_att + (size_t)sg[i] * 96 + h * 32 + td * 4) = o;
        }
    }
}

extern "C" void kernel_launch(void* const* d_in, const int* in_sizes, int n_in,
                              void* d_out, int out_size)
{
    (void)in_sizes; (void)n_in; (void)out_size;
    const float* x     = (const float*)d_in[0];
    const float* w_qkv = (const float*)d_in[1];
    const float* b_qkv = (const float*)d_in[2];
    const float* rel   = (const float*)d_in[3];
    const float* w_out = (const float*)d_in[4];
    const float* b_out = (const float*)d_in[5];
    float* out = (float*)d_out;

    float *qkv_p = nullptr, *att_p = nullptr;
    cudaGetSymbolAddress((void**)&qkv_p, g_qkv);
    cudaGetSymbolAddress((void**)&att_p, g_att);

    cudaFuncSetAttribute(gemm_f32x2, cudaFuncAttributeMaxDynamicSharedMemorySize, GEMM_SMEM);
    cudaFuncSetAttribute(attn2,      cudaFuncAttributeMaxDynamicSharedMemorySize, ATTN_SMEM);

    // 1) qkv = x @ w_qkv + b_qkv   (M=200704, N=288, K=96)
    gemm_f32x2<<<dim3(M_TOK / 128, 3), 192, GEMM_SMEM>>>(x, w_qkv, b_qkv, qkv_p, QKV_N);

    // 2) windowed attention (all heads per block), scatter to spatial layout
    attn2<<<4096, 192, ATTN_SMEM>>>(rel);

    // 3) out = att @ w_out + b_out  (N=96)
    gemm_f32x2<<<dim3(M_TOK / 128, 1), 192, GEMM_SMEM>>>(att_p, w_out, b_out, out, 96);
}